// round 1
// baseline (speedup 1.0000x reference)
#include <cuda_runtime.h>
#include <cstdint>

#define NN 100000
#define D  128

// Scratch (allocation-free rule: __device__ globals)
__device__ float g_h0[(size_t)NN * D];  // (1+eps)*x + agg
__device__ float g_h1[(size_t)NN * D];  // relu(h0@W1+b1)

// ---------------------------------------------------------------------------
// Kernel 1: h0 = (1+eps) * x   (vectorized float4, grid-stride not needed)
// ---------------------------------------------------------------------------
__global__ void init_kernel(const float* __restrict__ x,
                            const float* __restrict__ eps_p,
                            float* __restrict__ h0, int n4) {
    int i = blockIdx.x * blockDim.x + threadIdx.x;
    if (i >= n4) return;
    float s = 1.0f + __ldg(eps_p);
    float4 v = __ldg((const float4*)x + i);
    v.x *= s; v.y *= s; v.z *= s; v.w *= s;
    ((float4*)h0)[i] = v;
}

// ---------------------------------------------------------------------------
// Kernel 2: scatter-add. One warp per edge; each lane handles one float4
// chunk (32 lanes * 4 floats = 128). Vectorized red.global.add.v4.f32
// (PTX ISA 8.1+, sm_90+) quarters the atomic op count vs scalar atomicAdd.
// Reads of x[src] are fully coalesced (512B per warp).
// ---------------------------------------------------------------------------
__global__ void scatter_kernel(const float* __restrict__ x,
                               const int* __restrict__ src,
                               const int* __restrict__ dst,
                               float* __restrict__ h0, int n_edges) {
    int tid = blockIdx.x * blockDim.x + threadIdx.x;
    int e = tid >> 5;
    if (e >= n_edges) return;
    int lane = tid & 31;
    int s = __ldg(src + e);
    int d = __ldg(dst + e);
    float4 v = __ldg((const float4*)(x + (size_t)s * D) + lane);
    float* p = h0 + (size_t)d * D + lane * 4;
    asm volatile("red.global.add.v4.f32 [%0], {%1,%2,%3,%4};"
                 :: "l"(p), "f"(v.x), "f"(v.y), "f"(v.z), "f"(v.w)
                 : "memory");
}

// ---------------------------------------------------------------------------
// Kernel 3: C[M,128] = act(A[M,128] @ W[128,128] + bias)
// Register-tiled fp32 SGEMM: block tile 128x128, 256 threads, 8x8 per thread,
// K staged in 16-wide slices through shared memory.
// ---------------------------------------------------------------------------
template <bool RELU>
__global__ __launch_bounds__(256, 2)
void gemm_kernel(const float* __restrict__ A,
                 const float* __restrict__ W,
                 const float* __restrict__ bias,
                 float* __restrict__ C, int M) {
    __shared__ float As[16][128];  // [k][m]
    __shared__ float Bs[16][128];  // [k][n]

    const int tid = threadIdx.x;
    const int ty = tid >> 4;        // 0..15  (row group)
    const int tx = tid & 15;        // 0..15  (col group)
    const int row0 = blockIdx.x * 128;

    float acc[8][8];
#pragma unroll
    for (int i = 0; i < 8; i++)
#pragma unroll
        for (int j = 0; j < 8; j++) acc[i][j] = 0.0f;

    for (int k0 = 0; k0 < 128; k0 += 16) {
        // --- load A tile: 128 rows x 16 k, 512 float4s, 2 per thread ---
#pragma unroll
        for (int it = 0; it < 2; it++) {
            int f = tid + it * 256;          // float4 index 0..511
            int r = f >> 2;                  // row within tile
            int kk = (f & 3) << 2;           // k offset 0,4,8,12
            int grow = row0 + r;
            float4 v = make_float4(0.f, 0.f, 0.f, 0.f);
            if (grow < M)
                v = __ldg((const float4*)(A + (size_t)grow * 128 + k0) + (f & 3));
            As[kk + 0][r] = v.x;
            As[kk + 1][r] = v.y;
            As[kk + 2][r] = v.z;
            As[kk + 3][r] = v.w;
        }
        // --- load B tile: 16 k x 128 n, 512 float4s, 2 per thread ---
#pragma unroll
        for (int it = 0; it < 2; it++) {
            int f = tid + it * 256;
            int kr = f >> 5;                 // k row 0..15
            int nc = (f & 31) << 2;          // col 0..124
            float4 v = __ldg((const float4*)(W + (size_t)(k0 + kr) * 128 + nc));
            *(float4*)&Bs[kr][nc] = v;
        }
        __syncthreads();

#pragma unroll
        for (int k = 0; k < 16; k++) {
            float4 a0 = *(const float4*)&As[k][ty * 8];
            float4 a1 = *(const float4*)&As[k][ty * 8 + 4];
            float4 b0 = *(const float4*)&Bs[k][tx * 8];
            float4 b1 = *(const float4*)&Bs[k][tx * 8 + 4];
            float a[8] = {a0.x, a0.y, a0.z, a0.w, a1.x, a1.y, a1.z, a1.w};
            float b[8] = {b0.x, b0.y, b0.z, b0.w, b1.x, b1.y, b1.z, b1.w};
#pragma unroll
            for (int i = 0; i < 8; i++)
#pragma unroll
                for (int j = 0; j < 8; j++)
                    acc[i][j] = fmaf(a[i], b[j], acc[i][j]);
        }
        __syncthreads();
    }

    // epilogue
    float bv[8];
#pragma unroll
    for (int j = 0; j < 8; j++) bv[j] = __ldg(bias + tx * 8 + j);

#pragma unroll
    for (int i = 0; i < 8; i++) {
        int grow = row0 + ty * 8 + i;
        if (grow >= M) break;
        float4 o0, o1;
        float v[8];
#pragma unroll
        for (int j = 0; j < 8; j++) {
            float t = acc[i][j] + bv[j];
            if (RELU) t = fmaxf(t, 0.0f);
            v[j] = t;
        }
        o0 = make_float4(v[0], v[1], v[2], v[3]);
        o1 = make_float4(v[4], v[5], v[6], v[7]);
        float4* out = (float4*)(C + (size_t)grow * 128 + tx * 8);
        out[0] = o0;
        out[1] = o1;
    }
}

// ---------------------------------------------------------------------------
extern "C" void kernel_launch(void* const* d_in, const int* in_sizes, int n_in,
                              void* d_out, int out_size) {
    const float* x    = (const float*)d_in[0];
    const int*   ei   = (const int*)d_in[1];
    const float* W1   = (const float*)d_in[2];
    const float* b1   = (const float*)d_in[3];
    const float* W2   = (const float*)d_in[4];
    const float* b2   = (const float*)d_in[5];
    const float* eps  = (const float*)d_in[6];
    float*       out  = (float*)d_out;

    const int n_nodes = in_sizes[0] / D;
    const int n_edges = in_sizes[1] / 2;
    const int* src = ei;
    const int* dst = ei + n_edges;

    float* h0 = nullptr; cudaGetSymbolAddress((void**)&h0, g_h0);
    float* h1 = nullptr; cudaGetSymbolAddress((void**)&h1, g_h1);

    // 1) h0 = (1+eps)*x
    int n4 = n_nodes * D / 4;
    init_kernel<<<(n4 + 255) / 256, 256>>>(x, eps, h0, n4);

    // 2) h0 += scatter-add of x over edges
    long long sthreads = (long long)n_edges * 32;
    scatter_kernel<<<(int)((sthreads + 255) / 256), 256>>>(x, src, dst, h0, n_edges);

    // 3) h1 = relu(h0 @ W1 + b1)
    int gblocks = (n_nodes + 127) / 128;
    gemm_kernel<true><<<gblocks, 256>>>(h0, W1, b1, h1, n_nodes);

    // 4) out = h1 @ W2 + b2
    gemm_kernel<false><<<gblocks, 256>>>(h1, W2, b2, out, n_nodes);
}

// round 3
// speedup vs baseline: 1.3807x; 1.3807x over previous
#include <cuda_runtime.h>
#include <cstdint>

#define NN 100000
#define D  128

__device__ float g_h0[(size_t)NN * D];
__device__ float g_h1[(size_t)NN * D];
__device__ float g_W1t[D * D];
__device__ float g_W2t[D * D];

// ---------------------------------------------------------------------------
// Kernel 1: h0 = (1+eps) * x
// ---------------------------------------------------------------------------
__global__ void init_kernel(const float* __restrict__ x,
                            const float* __restrict__ eps_p,
                            float* __restrict__ h0, int n4) {
    int i = blockIdx.x * blockDim.x + threadIdx.x;
    if (i >= n4) return;
    float s = 1.0f + __ldg(eps_p);
    float4 v = __ldg((const float4*)x + i);
    v.x *= s; v.y *= s; v.z *= s; v.w *= s;
    ((float4*)h0)[i] = v;
}

// ---------------------------------------------------------------------------
// Kernel 2: scatter-add, one warp per edge, red.global.add.v4.f32
// ---------------------------------------------------------------------------
__global__ void scatter_kernel(const float* __restrict__ x,
                               const int* __restrict__ src,
                               const int* __restrict__ dst,
                               float* __restrict__ h0, int n_edges) {
    int tid = blockIdx.x * blockDim.x + threadIdx.x;
    int e = tid >> 5;
    if (e >= n_edges) return;
    int lane = tid & 31;
    int s = __ldg(src + e);
    int d = __ldg(dst + e);
    float4 v = __ldg((const float4*)(x + (size_t)s * D) + lane);
    float* p = h0 + (size_t)d * D + lane * 4;
    asm volatile("red.global.add.v4.f32 [%0], {%1,%2,%3,%4};"
                 :: "l"(p), "f"(v.x), "f"(v.y), "f"(v.z), "f"(v.w) : "memory");
}

// ---------------------------------------------------------------------------
// Kernel 2b: 128x128 transpose (W[k][n] -> Wt[n][k]) so B is k-contiguous per n
// ---------------------------------------------------------------------------
__global__ void transpose_kernel(const float* __restrict__ W, float* __restrict__ Wt) {
    __shared__ float t[32][33];
    int bx = blockIdx.x * 32, by = blockIdx.y * 32;
    int x = threadIdx.x, y = threadIdx.y;  // block (32,8)
#pragma unroll
    for (int i = 0; i < 32; i += 8)
        t[y + i][x] = W[(size_t)(by + y + i) * D + bx + x];
    __syncthreads();
#pragma unroll
    for (int i = 0; i < 32; i += 8)
        Wt[(size_t)(bx + y + i) * D + by + x] = t[x][y + i];
}

// ---------------------------------------------------------------------------
// mma.sync tf32 helpers (portable HMMA path; tcgen05 is fenced off by the
// toolchain's sm_103 base target)
// ---------------------------------------------------------------------------
__device__ __forceinline__ uint32_t f2tf32(float f) {
    uint32_t r;
    asm("cvt.rna.tf32.f32 %0, %1;" : "=r"(r) : "f"(f));
    return r;
}

__device__ __forceinline__ void mma_tf32(float* c, const uint32_t* a, const uint32_t* b) {
    asm volatile(
        "mma.sync.aligned.m16n8k8.row.col.f32.tf32.tf32.f32 "
        "{%0,%1,%2,%3}, {%4,%5,%6,%7}, {%8,%9}, {%0,%1,%2,%3};"
        : "+f"(c[0]), "+f"(c[1]), "+f"(c[2]), "+f"(c[3])
        : "r"(a[0]), "r"(a[1]), "r"(a[2]), "r"(a[3]),
          "r"(b[0]), "r"(b[1]));
}

// ---------------------------------------------------------------------------
// Kernel 3: tensor-core tf32 GEMM: C[M,128] = act(A[M,128] @ Wt^T + bias)
// Block 128x128, 8 warps in 2(M) x 4(N), warp tile 64x32, m16n8k8 HMMA.
// SMEM stride 132 floats -> fragment LDS addr%32 == lane (conflict-free).
// ---------------------------------------------------------------------------
#define LDS_STRIDE 132

template <bool RELU>
__global__ __launch_bounds__(256, 1)
void mma_gemm_kernel(const float* __restrict__ A,
                     const float* __restrict__ Wt,
                     const float* __restrict__ bias,
                     float* __restrict__ C, int M) {
    extern __shared__ float smem[];
    float* As = smem;                       // [128][132]
    float* Bs = smem + 128 * LDS_STRIDE;    // [128][132]  (Bs[n][k])

    const int tid = threadIdx.x;
    const int wid = tid >> 5;
    const int lid = tid & 31;
    const int wm = wid >> 2;            // 0..1 -> 64-row slab
    const int wn = wid & 3;             // 0..3 -> 32-col slab
    const int gid = lid >> 2;           // octet row group 0..7
    const int tig = lid & 3;            // 0..3
    const int row0 = blockIdx.x * 128;

    // --- load tiles (tf32-round at store time) ---
#pragma unroll
    for (int it = 0; it < 16; it++) {
        int idx = tid + it * 256;          // 0..4095 float4s
        int r = idx >> 5;
        int c4 = idx & 31;
        // A (guarded rows)
        float4 va = make_float4(0.f, 0.f, 0.f, 0.f);
        int grow = row0 + r;
        if (grow < M) va = __ldg((const float4*)(A + (size_t)grow * 128) + c4);
        uint32_t* ap = (uint32_t*)&As[r * LDS_STRIDE + c4 * 4];
        ap[0] = f2tf32(va.x); ap[1] = f2tf32(va.y);
        ap[2] = f2tf32(va.z); ap[3] = f2tf32(va.w);
        // B
        float4 vb = __ldg((const float4*)(Wt + (size_t)r * 128) + c4);
        uint32_t* bp = (uint32_t*)&Bs[r * LDS_STRIDE + c4 * 4];
        bp[0] = f2tf32(vb.x); bp[1] = f2tf32(vb.y);
        bp[2] = f2tf32(vb.z); bp[3] = f2tf32(vb.w);
    }
    __syncthreads();

    // --- mainloop: 16 K-chunks of 8 ---
    float acc[4][4][4];
#pragma unroll
    for (int mt = 0; mt < 4; mt++)
#pragma unroll
        for (int nt = 0; nt < 4; nt++)
#pragma unroll
            for (int q = 0; q < 4; q++) acc[mt][nt][q] = 0.0f;

#pragma unroll
    for (int k0 = 0; k0 < 128; k0 += 8) {
        uint32_t bfr[4][2];
#pragma unroll
        for (int nt = 0; nt < 4; nt++) {
            const uint32_t* bp = (const uint32_t*)
                &Bs[(wn * 32 + nt * 8 + gid) * LDS_STRIDE + k0 + tig];
            bfr[nt][0] = bp[0];
            bfr[nt][1] = bp[4];
        }
#pragma unroll
        for (int mt = 0; mt < 4; mt++) {
            uint32_t afr[4];
            const uint32_t* ap = (const uint32_t*)
                &As[(wm * 64 + mt * 16 + gid) * LDS_STRIDE + k0 + tig];
            afr[0] = ap[0];
            afr[1] = ap[8 * LDS_STRIDE];
            afr[2] = ap[4];
            afr[3] = ap[8 * LDS_STRIDE + 4];
#pragma unroll
            for (int nt = 0; nt < 4; nt++)
                mma_tf32(acc[mt][nt], afr, bfr[nt]);
        }
    }

    // --- epilogue: bias + activation, direct STG.64 ---
    float bv[4][2];
#pragma unroll
    for (int nt = 0; nt < 4; nt++) {
        int c0 = wn * 32 + nt * 8 + 2 * tig;
        bv[nt][0] = __ldg(bias + c0);
        bv[nt][1] = __ldg(bias + c0 + 1);
    }

#pragma unroll
    for (int mt = 0; mt < 4; mt++) {
        int r0 = row0 + wm * 64 + mt * 16 + gid;
        int r1 = r0 + 8;
#pragma unroll
        for (int nt = 0; nt < 4; nt++) {
            int c0 = wn * 32 + nt * 8 + 2 * tig;
            float2 v0, v1;
            v0.x = acc[mt][nt][0] + bv[nt][0];
            v0.y = acc[mt][nt][1] + bv[nt][1];
            v1.x = acc[mt][nt][2] + bv[nt][0];
            v1.y = acc[mt][nt][3] + bv[nt][1];
            if (RELU) {
                v0.x = fmaxf(v0.x, 0.f); v0.y = fmaxf(v0.y, 0.f);
                v1.x = fmaxf(v1.x, 0.f); v1.y = fmaxf(v1.y, 0.f);
            }
            if (r0 < M) *(float2*)(C + (size_t)r0 * 128 + c0) = v0;
            if (r1 < M) *(float2*)(C + (size_t)r1 * 128 + c0) = v1;
        }
    }
}

// ---------------------------------------------------------------------------
extern "C" void kernel_launch(void* const* d_in, const int* in_sizes, int n_in,
                              void* d_out, int out_size) {
    const float* x   = (const float*)d_in[0];
    const int*   ei  = (const int*)d_in[1];
    const float* W1  = (const float*)d_in[2];
    const float* b1  = (const float*)d_in[3];
    const float* W2  = (const float*)d_in[4];
    const float* b2  = (const float*)d_in[5];
    const float* eps = (const float*)d_in[6];
    float*       out = (float*)d_out;

    const int n_nodes = in_sizes[0] / D;
    const int n_edges = in_sizes[1] / 2;
    const int* src = ei;
    const int* dst = ei + n_edges;

    float *h0, *h1, *w1t, *w2t;
    cudaGetSymbolAddress((void**)&h0, g_h0);
    cudaGetSymbolAddress((void**)&h1, g_h1);
    cudaGetSymbolAddress((void**)&w1t, g_W1t);
    cudaGetSymbolAddress((void**)&w2t, g_W2t);

    const int SMEM = 2 * 128 * LDS_STRIDE * (int)sizeof(float);  // 135168
    cudaFuncSetAttribute(mma_gemm_kernel<true>,
                         cudaFuncAttributeMaxDynamicSharedMemorySize, SMEM);
    cudaFuncSetAttribute(mma_gemm_kernel<false>,
                         cudaFuncAttributeMaxDynamicSharedMemorySize, SMEM);

    int n4 = n_nodes * D / 4;
    init_kernel<<<(n4 + 255) / 256, 256>>>(x, eps, h0, n4);

    long long sthreads = (long long)n_edges * 32;
    scatter_kernel<<<(int)((sthreads + 255) / 256), 256>>>(x, src, dst, h0, n_edges);

    dim3 tb(32, 8), tg(4, 4);
    transpose_kernel<<<tg, tb>>>(W1, w1t);
    transpose_kernel<<<tg, tb>>>(W2, w2t);

    int gblocks = (n_nodes + 127) / 128;
    mma_gemm_kernel<true><<<gblocks, 256, SMEM>>>(h0, w1t, b1, h1, n_nodes);
    mma_gemm_kernel<false><<<gblocks, 256, SMEM>>>(h1, w2t, b2, out, n_nodes);
}

// round 4
// speedup vs baseline: 2.2209x; 1.6086x over previous
#include <cuda_runtime.h>
#include <cstdint>

#define NN 100000
#define NE 1600000
#define D  128
#define SCAN_B 1024

__device__ float g_h0[(size_t)NN * D];
__device__ float g_h1[(size_t)NN * D];
__device__ float g_W1t[D * D];
__device__ float g_W2t[D * D];
__device__ int   g_deg[NN];
__device__ int   g_off[NN + 1];
__device__ int   g_cur[NN];
__device__ int   g_bsum[(NN + SCAN_B - 1) / SCAN_B];
__device__ int   g_boff[(NN + SCAN_B - 1) / SCAN_B];
__device__ int   g_csr[NE];

// ---------------------------------------------------------------------------
// CSR build
// ---------------------------------------------------------------------------
__global__ void zero_deg_kernel(int n) {
    int i = blockIdx.x * blockDim.x + threadIdx.x;
    if (i < n) g_deg[i] = 0;
}

__global__ void count_kernel(const int* __restrict__ dst, int n_edges) {
    int e = blockIdx.x * blockDim.x + threadIdx.x;
    if (e < n_edges) atomicAdd(&g_deg[__ldg(dst + e)], 1);
}

// Per-block inclusive scan (Hillis-Steele); writes local-exclusive to off,
// block total to bsum.
__global__ __launch_bounds__(SCAN_B)
void scan1_kernel(int n) {
    __shared__ int s[SCAN_B];
    int tid = threadIdx.x;
    int gi = blockIdx.x * SCAN_B + tid;
    int v = (gi < n) ? g_deg[gi] : 0;
    s[tid] = v;
    __syncthreads();
#pragma unroll
    for (int d = 1; d < SCAN_B; d <<= 1) {
        int t = (tid >= d) ? s[tid - d] : 0;
        __syncthreads();
        s[tid] += t;
        __syncthreads();
    }
    if (gi < n) g_off[gi] = s[tid] - v;          // local exclusive
    if (tid == SCAN_B - 1) g_bsum[blockIdx.x] = s[tid];
}

__global__ void scan2_kernel(int nblocks) {
    __shared__ int s[256];
    int tid = threadIdx.x;
    int v = (tid < nblocks) ? g_bsum[tid] : 0;
    s[tid] = v;
    __syncthreads();
#pragma unroll
    for (int d = 1; d < 256; d <<= 1) {
        int t = (tid >= d) ? s[tid - d] : 0;
        __syncthreads();
        s[tid] += t;
        __syncthreads();
    }
    if (tid < nblocks) g_boff[tid] = s[tid] - v; // exclusive
}

__global__ void add_off_kernel(int n, int n_edges) {
    int i = blockIdx.x * blockDim.x + threadIdx.x;
    if (i < n) {
        int o = g_off[i] + g_boff[i / SCAN_B];
        g_off[i] = o;
        g_cur[i] = o;
    }
    if (i == 0) g_off[n] = n_edges;
}

__global__ void fill_kernel(const int* __restrict__ src,
                            const int* __restrict__ dst, int n_edges) {
    int e = blockIdx.x * blockDim.x + threadIdx.x;
    if (e < n_edges) {
        int p = atomicAdd(&g_cur[__ldg(dst + e)], 1);
        g_csr[p] = __ldg(src + e);
    }
}

// ---------------------------------------------------------------------------
// Gather: one warp per node. h0 = (1+eps)*x[node] + sum_{j in N(node)} x[j]
// Full 512B rows read coalesced per edge; x is L2-resident.
// ---------------------------------------------------------------------------
__global__ __launch_bounds__(256)
void gather_kernel(const float* __restrict__ x,
                   const float* __restrict__ eps_p,
                   float* __restrict__ h0, int n_nodes) {
    int warp = (blockIdx.x * blockDim.x + threadIdx.x) >> 5;
    if (warp >= n_nodes) return;
    int lane = threadIdx.x & 31;

    int beg = __ldg(&g_off[warp]);
    int end = __ldg(&g_off[warp + 1]);
    float s = 1.0f + __ldg(eps_p);

    const float4* x4 = (const float4*)x;
    float4 v = __ldg(x4 + (size_t)warp * 32 + lane);
    float4 acc = make_float4(v.x * s, v.y * s, v.z * s, v.w * s);

    for (int b = beg; b < end; b += 32) {
        int cnt = min(32, end - b);
        int idx = (lane < cnt) ? __ldg(&g_csr[b + lane]) : 0;
        for (int j = 0; j < cnt; j++) {
            int sj = __shfl_sync(0xffffffffu, idx, j);
            float4 w = __ldg(x4 + (size_t)sj * 32 + lane);
            acc.x += w.x; acc.y += w.y; acc.z += w.z; acc.w += w.w;
        }
    }
    ((float4*)h0)[(size_t)warp * 32 + lane] = acc;
}

// ---------------------------------------------------------------------------
// Weight transposes (both in one launch; z selects matrix)
// ---------------------------------------------------------------------------
__global__ void transpose_kernel(const float* __restrict__ W1, float* __restrict__ W1t,
                                 const float* __restrict__ W2, float* __restrict__ W2t) {
    __shared__ float t[32][33];
    const float* W  = blockIdx.z ? W2 : W1;
    float*       Wt = blockIdx.z ? W2t : W1t;
    int bx = blockIdx.x * 32, by = blockIdx.y * 32;
    int x = threadIdx.x, y = threadIdx.y;  // block (32,8)
#pragma unroll
    for (int i = 0; i < 32; i += 8)
        t[y + i][x] = W[(size_t)(by + y + i) * D + bx + x];
    __syncthreads();
#pragma unroll
    for (int i = 0; i < 32; i += 8)
        Wt[(size_t)(bx + y + i) * D + by + x] = t[x][y + i];
}

// ---------------------------------------------------------------------------
// mma.sync tf32 GEMM (portable HMMA; tcgen05 is fenced off by base sm_103)
// ---------------------------------------------------------------------------
__device__ __forceinline__ uint32_t f2tf32(float f) {
    uint32_t r;
    asm("cvt.rna.tf32.f32 %0, %1;" : "=r"(r) : "f"(f));
    return r;
}

__device__ __forceinline__ void mma_tf32(float* c, const uint32_t* a, const uint32_t* b) {
    asm volatile(
        "mma.sync.aligned.m16n8k8.row.col.f32.tf32.tf32.f32 "
        "{%0,%1,%2,%3}, {%4,%5,%6,%7}, {%8,%9}, {%0,%1,%2,%3};"
        : "+f"(c[0]), "+f"(c[1]), "+f"(c[2]), "+f"(c[3])
        : "r"(a[0]), "r"(a[1]), "r"(a[2]), "r"(a[3]),
          "r"(b[0]), "r"(b[1]));
}

#define LDS_STRIDE 132

template <bool RELU>
__global__ __launch_bounds__(256, 1)
void mma_gemm_kernel(const float* __restrict__ A,
                     const float* __restrict__ Wt,
                     const float* __restrict__ bias,
                     float* __restrict__ C, int M) {
    extern __shared__ float smem[];
    float* As = smem;                       // [128][132]
    float* Bs = smem + 128 * LDS_STRIDE;    // [128][132]  (Bs[n][k])

    const int tid = threadIdx.x;
    const int wid = tid >> 5;
    const int lid = tid & 31;
    const int wm = wid >> 2;
    const int wn = wid & 3;
    const int gid = lid >> 2;
    const int tig = lid & 3;
    const int row0 = blockIdx.x * 128;

#pragma unroll
    for (int it = 0; it < 16; it++) {
        int idx = tid + it * 256;
        int r = idx >> 5;
        int c4 = idx & 31;
        float4 va = make_float4(0.f, 0.f, 0.f, 0.f);
        int grow = row0 + r;
        if (grow < M) va = __ldg((const float4*)(A + (size_t)grow * 128) + c4);
        uint32_t* ap = (uint32_t*)&As[r * LDS_STRIDE + c4 * 4];
        ap[0] = f2tf32(va.x); ap[1] = f2tf32(va.y);
        ap[2] = f2tf32(va.z); ap[3] = f2tf32(va.w);
        float4 vb = __ldg((const float4*)(Wt + (size_t)r * 128) + c4);
        uint32_t* bp = (uint32_t*)&Bs[r * LDS_STRIDE + c4 * 4];
        bp[0] = f2tf32(vb.x); bp[1] = f2tf32(vb.y);
        bp[2] = f2tf32(vb.z); bp[3] = f2tf32(vb.w);
    }
    __syncthreads();

    float acc[4][4][4];
#pragma unroll
    for (int mt = 0; mt < 4; mt++)
#pragma unroll
        for (int nt = 0; nt < 4; nt++)
#pragma unroll
            for (int q = 0; q < 4; q++) acc[mt][nt][q] = 0.0f;

#pragma unroll
    for (int k0 = 0; k0 < 128; k0 += 8) {
        uint32_t bfr[4][2];
#pragma unroll
        for (int nt = 0; nt < 4; nt++) {
            const uint32_t* bp = (const uint32_t*)
                &Bs[(wn * 32 + nt * 8 + gid) * LDS_STRIDE + k0 + tig];
            bfr[nt][0] = bp[0];
            bfr[nt][1] = bp[4];
        }
#pragma unroll
        for (int mt = 0; mt < 4; mt++) {
            uint32_t afr[4];
            const uint32_t* ap = (const uint32_t*)
                &As[(wm * 64 + mt * 16 + gid) * LDS_STRIDE + k0 + tig];
            afr[0] = ap[0];
            afr[1] = ap[8 * LDS_STRIDE];
            afr[2] = ap[4];
            afr[3] = ap[8 * LDS_STRIDE + 4];
#pragma unroll
            for (int nt = 0; nt < 4; nt++)
                mma_tf32(acc[mt][nt], afr, bfr[nt]);
        }
    }

    float bv[4][2];
#pragma unroll
    for (int nt = 0; nt < 4; nt++) {
        int c0 = wn * 32 + nt * 8 + 2 * tig;
        bv[nt][0] = __ldg(bias + c0);
        bv[nt][1] = __ldg(bias + c0 + 1);
    }

#pragma unroll
    for (int mt = 0; mt < 4; mt++) {
        int r0 = row0 + wm * 64 + mt * 16 + gid;
        int r1 = r0 + 8;
#pragma unroll
        for (int nt = 0; nt < 4; nt++) {
            int c0 = wn * 32 + nt * 8 + 2 * tig;
            float2 v0, v1;
            v0.x = acc[mt][nt][0] + bv[nt][0];
            v0.y = acc[mt][nt][1] + bv[nt][1];
            v1.x = acc[mt][nt][2] + bv[nt][0];
            v1.y = acc[mt][nt][3] + bv[nt][1];
            if (RELU) {
                v0.x = fmaxf(v0.x, 0.f); v0.y = fmaxf(v0.y, 0.f);
                v1.x = fmaxf(v1.x, 0.f); v1.y = fmaxf(v1.y, 0.f);
            }
            if (r0 < M) *(float2*)(C + (size_t)r0 * 128 + c0) = v0;
            if (r1 < M) *(float2*)(C + (size_t)r1 * 128 + c0) = v1;
        }
    }
}

// ---------------------------------------------------------------------------
extern "C" void kernel_launch(void* const* d_in, const int* in_sizes, int n_in,
                              void* d_out, int out_size) {
    const float* x   = (const float*)d_in[0];
    const int*   ei  = (const int*)d_in[1];
    const float* W1  = (const float*)d_in[2];
    const float* b1  = (const float*)d_in[3];
    const float* W2  = (const float*)d_in[4];
    const float* b2  = (const float*)d_in[5];
    const float* eps = (const float*)d_in[6];
    float*       out = (float*)d_out;

    const int n_nodes = in_sizes[0] / D;
    const int n_edges = in_sizes[1] / 2;
    const int* src = ei;
    const int* dst = ei + n_edges;

    float *h0, *h1, *w1t, *w2t;
    cudaGetSymbolAddress((void**)&h0, g_h0);
    cudaGetSymbolAddress((void**)&h1, g_h1);
    cudaGetSymbolAddress((void**)&w1t, g_W1t);
    cudaGetSymbolAddress((void**)&w2t, g_W2t);

    const int SMEM = 2 * 128 * LDS_STRIDE * (int)sizeof(float);
    cudaFuncSetAttribute(mma_gemm_kernel<true>,
                         cudaFuncAttributeMaxDynamicSharedMemorySize, SMEM);
    cudaFuncSetAttribute(mma_gemm_kernel<false>,
                         cudaFuncAttributeMaxDynamicSharedMemorySize, SMEM);

    // ---- CSR build ----
    int nscan = (n_nodes + SCAN_B - 1) / SCAN_B;
    zero_deg_kernel<<<(n_nodes + 255) / 256, 256>>>(n_nodes);
    count_kernel<<<(n_edges + 255) / 256, 256>>>(dst, n_edges);
    scan1_kernel<<<nscan, SCAN_B>>>(n_nodes);
    scan2_kernel<<<1, 256>>>(nscan);
    add_off_kernel<<<(n_nodes + 255) / 256, 256>>>(n_nodes, n_edges);
    fill_kernel<<<(n_edges + 255) / 256, 256>>>(src, dst, n_edges);

    // ---- fused init + aggregation ----
    int gwarps = (n_nodes * 32 + 255) / 256;
    gather_kernel<<<gwarps, 256>>>(x, eps, h0, n_nodes);

    // ---- weights transpose (single launch) ----
    dim3 tb(32, 8), tg(4, 4, 2);
    transpose_kernel<<<tg, tb>>>(W1, w1t, W2, w2t);

    // ---- MLP ----
    int gblocks = (n_nodes + 127) / 128;
    mma_gemm_kernel<true><<<gblocks, 256, SMEM>>>(h0, w1t, b1, h1, n_nodes);
    mma_gemm_kernel<false><<<gblocks, 256, SMEM>>>(h1, w2t, b2, out, n_nodes);
}

// round 5
// speedup vs baseline: 2.5658x; 1.1553x over previous
#include <cuda_runtime.h>
#include <cstdint>

#define NN  100000
#define NE  1600000
#define D   128
#define CAP 128   // slots per node; overflow handled exactly via side list

__device__ float g_h0[(size_t)NN * D];
__device__ float g_W1t[D * D];
__device__ float g_W2t[D * D];
__device__ int   g_cnt[NN];
__device__ int   g_slot[(size_t)NN * CAP];
__device__ int   g_ovf_n;
__device__ int2  g_ovf[NE];

// ---------------------------------------------------------------------------
// Kernel 1: zero counters (graph replays -> must reset every call)
// ---------------------------------------------------------------------------
__global__ void zero_kernel(int n) {
    int i = blockIdx.x * blockDim.x + threadIdx.x;
    if (i < n) g_cnt[i] = 0;
    if (i == 0) g_ovf_n = 0;
}

// ---------------------------------------------------------------------------
// Kernel 2: binned fill. One thread per edge.
// ---------------------------------------------------------------------------
__global__ void fill_kernel(const int* __restrict__ src,
                            const int* __restrict__ dst, int n_edges) {
    int e = blockIdx.x * blockDim.x + threadIdx.x;
    if (e >= n_edges) return;
    int s = __ldg(src + e);
    int d = __ldg(dst + e);
    int p = atomicAdd(&g_cnt[d], 1);
    if (p < CAP) {
        g_slot[(size_t)d * CAP + p] = s;
    } else {
        int q = atomicAdd(&g_ovf_n, 1);
        g_ovf[q] = make_int2(s, d);
    }
}

// ---------------------------------------------------------------------------
// Kernel 3: gather. One warp per node:
//   h0 = (1+eps)*x[node] + sum_{j in slots(node)} x[j]
// ---------------------------------------------------------------------------
__global__ __launch_bounds__(256)
void gather_kernel(const float* __restrict__ x,
                   const float* __restrict__ eps_p,
                   float* __restrict__ h0, int n_nodes) {
    int warp = (blockIdx.x * blockDim.x + threadIdx.x) >> 5;
    if (warp >= n_nodes) return;
    int lane = threadIdx.x & 31;

    int cnt = min(__ldg(&g_cnt[warp]), CAP);
    float s = 1.0f + __ldg(eps_p);

    const float4* x4 = (const float4*)x;
    float4 v = __ldg(x4 + (size_t)warp * 32 + lane);
    float4 acc = make_float4(v.x * s, v.y * s, v.z * s, v.w * s);

    const int* slots = g_slot + (size_t)warp * CAP;
    for (int b = 0; b < cnt; b += 32) {
        int c = min(32, cnt - b);
        int idx = (lane < c) ? __ldg(slots + b + lane) : 0;
        for (int j = 0; j < c; j++) {
            int sj = __shfl_sync(0xffffffffu, idx, j);
            float4 w = __ldg(x4 + (size_t)sj * 32 + lane);
            acc.x += w.x; acc.y += w.y; acc.z += w.z; acc.w += w.w;
        }
    }
    ((float4*)h0)[(size_t)warp * 32 + lane] = acc;
}

// ---------------------------------------------------------------------------
// Kernel 4: overflow fixup (exact-correctness path; 0 entries in practice).
// One warp per overflow edge, red.global.add.v4 into h0.
// ---------------------------------------------------------------------------
__global__ void ovf_kernel(const float* __restrict__ x, float* __restrict__ h0) {
    int n = g_ovf_n;
    if (n <= 0) return;
    int wid = threadIdx.x >> 5;
    int lane = threadIdx.x & 31;
    for (int e = wid; e < n; e += 8) {
        int2 sd = g_ovf[e];
        float4 v = __ldg((const float4*)(x + (size_t)sd.x * D) + lane);
        float* p = h0 + (size_t)sd.y * D + lane * 4;
        asm volatile("red.global.add.v4.f32 [%0], {%1,%2,%3,%4};"
                     :: "l"(p), "f"(v.x), "f"(v.y), "f"(v.z), "f"(v.w) : "memory");
    }
}

// ---------------------------------------------------------------------------
// Kernel 5: weight transposes (both matrices, z selects)
// ---------------------------------------------------------------------------
__global__ void transpose_kernel(const float* __restrict__ W1, float* __restrict__ W1t,
                                 const float* __restrict__ W2, float* __restrict__ W2t) {
    __shared__ float t[32][33];
    const float* W  = blockIdx.z ? W2 : W1;
    float*       Wt = blockIdx.z ? W2t : W1t;
    int bx = blockIdx.x * 32, by = blockIdx.y * 32;
    int x = threadIdx.x, y = threadIdx.y;  // block (32,8)
#pragma unroll
    for (int i = 0; i < 32; i += 8)
        t[y + i][x] = W[(size_t)(by + y + i) * D + bx + x];
    __syncthreads();
#pragma unroll
    for (int i = 0; i < 32; i += 8)
        Wt[(size_t)(bx + y + i) * D + by + x] = t[x][y + i];
}

// ---------------------------------------------------------------------------
// mma.sync tf32 helpers (portable HMMA; tcgen05 fenced off by base sm_103)
// ---------------------------------------------------------------------------
__device__ __forceinline__ uint32_t f2tf32(float f) {
    uint32_t r;
    asm("cvt.rna.tf32.f32 %0, %1;" : "=r"(r) : "f"(f));
    return r;
}
__device__ __forceinline__ void mma_tf32(float* c, const uint32_t* a, const uint32_t* b) {
    asm volatile(
        "mma.sync.aligned.m16n8k8.row.col.f32.tf32.tf32.f32 "
        "{%0,%1,%2,%3}, {%4,%5,%6,%7}, {%8,%9}, {%0,%1,%2,%3};"
        : "+f"(c[0]), "+f"(c[1]), "+f"(c[2]), "+f"(c[3])
        : "r"(a[0]), "r"(a[1]), "r"(a[2]), "r"(a[3]),
          "r"(b[0]), "r"(b[1]));
}

#define LDS_STRIDE 132

// ---------------------------------------------------------------------------
// Kernel 6: fused MLP. out = relu(h0@W1t^T + b1) @ W2t^T + b2, one CTA per
// 128-row tile. Mainloop1 -> relu tile restored to SMEM -> mainloop2.
// ---------------------------------------------------------------------------
__global__ __launch_bounds__(256, 1)
void fused_mlp_kernel(const float* __restrict__ A,
                      const float* __restrict__ W1t,
                      const float* __restrict__ b1,
                      const float* __restrict__ W2t,
                      const float* __restrict__ b2,
                      float* __restrict__ C, int M) {
    extern __shared__ float smem[];
    float* As = smem;                       // [128][132]
    float* Bs = smem + 128 * LDS_STRIDE;    // [128][132] (weights, [n][k])

    const int tid = threadIdx.x;
    const int wid = tid >> 5;
    const int lid = tid & 31;
    const int wm = wid >> 2;
    const int wn = wid & 3;
    const int gid = lid >> 2;
    const int tig = lid & 3;
    const int row0 = blockIdx.x * 128;

    // ---- load A tile + W1 ----
#pragma unroll
    for (int it = 0; it < 16; it++) {
        int idx = tid + it * 256;
        int r = idx >> 5;
        int c4 = idx & 31;
        float4 va = make_float4(0.f, 0.f, 0.f, 0.f);
        int grow = row0 + r;
        if (grow < M) va = __ldg((const float4*)(A + (size_t)grow * 128) + c4);
        uint32_t* ap = (uint32_t*)&As[r * LDS_STRIDE + c4 * 4];
        ap[0] = f2tf32(va.x); ap[1] = f2tf32(va.y);
        ap[2] = f2tf32(va.z); ap[3] = f2tf32(va.w);
        float4 vb = __ldg((const float4*)(W1t + (size_t)r * 128) + c4);
        uint32_t* bp = (uint32_t*)&Bs[r * LDS_STRIDE + c4 * 4];
        bp[0] = f2tf32(vb.x); bp[1] = f2tf32(vb.y);
        bp[2] = f2tf32(vb.z); bp[3] = f2tf32(vb.w);
    }
    __syncthreads();

    float acc[4][4][4];
#pragma unroll
    for (int mt = 0; mt < 4; mt++)
#pragma unroll
        for (int nt = 0; nt < 4; nt++)
#pragma unroll
            for (int q = 0; q < 4; q++) acc[mt][nt][q] = 0.0f;

    // ---- mainloop 1 ----
#pragma unroll
    for (int k0 = 0; k0 < 128; k0 += 8) {
        uint32_t bfr[4][2];
#pragma unroll
        for (int nt = 0; nt < 4; nt++) {
            const uint32_t* bp = (const uint32_t*)
                &Bs[(wn * 32 + nt * 8 + gid) * LDS_STRIDE + k0 + tig];
            bfr[nt][0] = bp[0];
            bfr[nt][1] = bp[4];
        }
#pragma unroll
        for (int mt = 0; mt < 4; mt++) {
            uint32_t afr[4];
            const uint32_t* ap = (const uint32_t*)
                &As[(wm * 64 + mt * 16 + gid) * LDS_STRIDE + k0 + tig];
            afr[0] = ap[0];
            afr[1] = ap[8 * LDS_STRIDE];
            afr[2] = ap[4];
            afr[3] = ap[8 * LDS_STRIDE + 4];
#pragma unroll
            for (int nt = 0; nt < 4; nt++)
                mma_tf32(acc[mt][nt], afr, bfr[nt]);
        }
    }
    __syncthreads();   // all reads of As/Bs done before overwrite

    // ---- relu(acc + b1) back into As (tf32), reload Bs = W2 ----
#pragma unroll
    for (int mt = 0; mt < 4; mt++) {
        int r0 = wm * 64 + mt * 16 + gid;
#pragma unroll
        for (int nt = 0; nt < 4; nt++) {
            int c0 = wn * 32 + nt * 8 + 2 * tig;
            float bb0 = __ldg(b1 + c0), bb1 = __ldg(b1 + c0 + 1);
            uint32_t* p0 = (uint32_t*)&As[r0 * LDS_STRIDE + c0];
            uint32_t* p1 = (uint32_t*)&As[(r0 + 8) * LDS_STRIDE + c0];
            p0[0] = f2tf32(fmaxf(acc[mt][nt][0] + bb0, 0.f));
            p0[1] = f2tf32(fmaxf(acc[mt][nt][1] + bb1, 0.f));
            p1[0] = f2tf32(fmaxf(acc[mt][nt][2] + bb0, 0.f));
            p1[1] = f2tf32(fmaxf(acc[mt][nt][3] + bb1, 0.f));
        }
    }
#pragma unroll
    for (int it = 0; it < 8; it++) {
        int idx = tid + it * 256;
        int r = idx >> 4;
        int c4 = idx & 15;                 // 8 float4s per 2 threads? no:
        // 128 rows x 32 float4s = 4096; with 2048 iterations need c4 0..31:
        // redo mapping: idx in [0,2048), handle two float4s each
        int cA = c4 * 2;
        float4 vb = __ldg((const float4*)(W2t + (size_t)r * 128) + cA);
        uint32_t* bp = (uint32_t*)&Bs[r * LDS_STRIDE + cA * 4];
        bp[0] = f2tf32(vb.x); bp[1] = f2tf32(vb.y);
        bp[2] = f2tf32(vb.z); bp[3] = f2tf32(vb.w);
        float4 vb2 = __ldg((const float4*)(W2t + (size_t)r * 128) + cA + 1);
        uint32_t* bp2 = (uint32_t*)&Bs[r * LDS_STRIDE + (cA + 1) * 4];
        bp2[0] = f2tf32(vb2.x); bp2[1] = f2tf32(vb2.y);
        bp2[2] = f2tf32(vb2.z); bp2[3] = f2tf32(vb2.w);
    }
    __syncthreads();

    // ---- mainloop 2 ----
#pragma unroll
    for (int mt = 0; mt < 4; mt++)
#pragma unroll
        for (int nt = 0; nt < 4; nt++)
#pragma unroll
            for (int q = 0; q < 4; q++) acc[mt][nt][q] = 0.0f;

#pragma unroll
    for (int k0 = 0; k0 < 128; k0 += 8) {
        uint32_t bfr[4][2];
#pragma unroll
        for (int nt = 0; nt < 4; nt++) {
            const uint32_t* bp = (const uint32_t*)
                &Bs[(wn * 32 + nt * 8 + gid) * LDS_STRIDE + k0 + tig];
            bfr[nt][0] = bp[0];
            bfr[nt][1] = bp[4];
        }
#pragma unroll
        for (int mt = 0; mt < 4; mt++) {
            uint32_t afr[4];
            const uint32_t* ap = (const uint32_t*)
                &As[(wm * 64 + mt * 16 + gid) * LDS_STRIDE + k0 + tig];
            afr[0] = ap[0];
            afr[1] = ap[8 * LDS_STRIDE];
            afr[2] = ap[4];
            afr[3] = ap[8 * LDS_STRIDE + 4];
#pragma unroll
            for (int nt = 0; nt < 4; nt++)
                mma_tf32(acc[mt][nt], afr, bfr[nt]);
        }
    }

    // ---- epilogue to global ----
#pragma unroll
    for (int mt = 0; mt < 4; mt++) {
        int r0 = row0 + wm * 64 + mt * 16 + gid;
        int r1 = r0 + 8;
#pragma unroll
        for (int nt = 0; nt < 4; nt++) {
            int c0 = wn * 32 + nt * 8 + 2 * tig;
            float bb0 = __ldg(b2 + c0), bb1 = __ldg(b2 + c0 + 1);
            float2 v0 = make_float2(acc[mt][nt][0] + bb0, acc[mt][nt][1] + bb1);
            float2 v1 = make_float2(acc[mt][nt][2] + bb0, acc[mt][nt][3] + bb1);
            if (r0 < M) *(float2*)(C + (size_t)r0 * 128 + c0) = v0;
            if (r1 < M) *(float2*)(C + (size_t)r1 * 128 + c0) = v1;
        }
    }
}

// ---------------------------------------------------------------------------
extern "C" void kernel_launch(void* const* d_in, const int* in_sizes, int n_in,
                              void* d_out, int out_size) {
    const float* x   = (const float*)d_in[0];
    const int*   ei  = (const int*)d_in[1];
    const float* W1  = (const float*)d_in[2];
    const float* b1  = (const float*)d_in[3];
    const float* W2  = (const float*)d_in[4];
    const float* b2  = (const float*)d_in[5];
    const float* eps = (const float*)d_in[6];
    float*       out = (float*)d_out;

    const int n_nodes = in_sizes[0] / D;
    const int n_edges = in_sizes[1] / 2;
    const int* src = ei;
    const int* dst = ei + n_edges;

    float *h0, *w1t, *w2t;
    cudaGetSymbolAddress((void**)&h0, g_h0);
    cudaGetSymbolAddress((void**)&w1t, g_W1t);
    cudaGetSymbolAddress((void**)&w2t, g_W2t);

    const int SMEM = 2 * 128 * LDS_STRIDE * (int)sizeof(float);
    cudaFuncSetAttribute(fused_mlp_kernel,
                         cudaFuncAttributeMaxDynamicSharedMemorySize, SMEM);

    zero_kernel<<<(n_nodes + 255) / 256, 256>>>(n_nodes);
    fill_kernel<<<(n_edges + 255) / 256, 256>>>(src, dst, n_edges);

    int gwarps = (n_nodes * 32 + 255) / 256;
    gather_kernel<<<gwarps, 256>>>(x, eps, h0, n_nodes);
    ovf_kernel<<<1, 256>>>(x, h0);

    dim3 tb(32, 8), tg(4, 4, 2);
    transpose_kernel<<<tg, tb>>>(W1, w1t, W2, w2t);

    int gblocks = (n_nodes + 127) / 128;
    fused_mlp_kernel<<<gblocks, 256, SMEM>>>(h0, w1t, b1, w2t, b2, out, n_nodes);
}

// round 6
// speedup vs baseline: 2.5776x; 1.0046x over previous
#include <cuda_runtime.h>
#include <cstdint>

#define NN  100000
#define NE  1600000
#define D   128
#define CAP 64   // slots per node; overflow handled exactly via side list

__device__ float g_h0[(size_t)NN * D];
__device__ float g_W1t[D * D];
__device__ float g_W2t[D * D];
__device__ int   g_cnt[NN];
__device__ int   g_slot[(size_t)NN * CAP];
__device__ int   g_ovf_n;
__device__ int2  g_ovf[NE];

// ---------------------------------------------------------------------------
// Kernel 1: zero counters (graph replays -> must reset every call)
// ---------------------------------------------------------------------------
__global__ void zero_kernel(int n) {
    int i = blockIdx.x * blockDim.x + threadIdx.x;
    if (i < n) g_cnt[i] = 0;
    if (i == 0) g_ovf_n = 0;
}

// ---------------------------------------------------------------------------
// Kernel 2: binned fill (blocks [0, n_fill)) + weight transposes (32 tail
// blocks). One thread per edge; transpose tails: 32x32 tiles, z selects W.
// ---------------------------------------------------------------------------
__global__ __launch_bounds__(256)
void fill_kernel(const int* __restrict__ src,
                 const int* __restrict__ dst, int n_edges, int n_fill,
                 const float* __restrict__ W1, float* __restrict__ W1t,
                 const float* __restrict__ W2, float* __restrict__ W2t) {
    __shared__ float t[32][33];
    if (blockIdx.x >= n_fill) {
        int bid = blockIdx.x - n_fill;        // 0..31
        const float* W  = (bid & 16) ? W2 : W1;
        float*       Wt = (bid & 16) ? W2t : W1t;
        int bx = (bid & 3) * 32, by = ((bid >> 2) & 3) * 32;
        int x = threadIdx.x & 31, y = threadIdx.x >> 5;   // (32,8)
#pragma unroll
        for (int i = 0; i < 32; i += 8)
            t[y + i][x] = W[(size_t)(by + y + i) * D + bx + x];
        __syncthreads();
#pragma unroll
        for (int i = 0; i < 32; i += 8)
            Wt[(size_t)(bx + y + i) * D + by + x] = t[x][y + i];
        return;
    }
    int e = blockIdx.x * blockDim.x + threadIdx.x;
    if (e >= n_edges) return;
    int s = __ldg(src + e);
    int d = __ldg(dst + e);
    int p = atomicAdd(&g_cnt[d], 1);
    if (p < CAP) {
        g_slot[(size_t)d * CAP + p] = s;
    } else {
        int q = atomicAdd(&g_ovf_n, 1);
        g_ovf[q] = make_int2(s, d);
    }
}

// ---------------------------------------------------------------------------
// Kernel 3: gather. One warp per node:
//   h0 = (1+eps)*x[node] + sum_{j in slots(node)} x[j]  (+ exact ovf fixup)
// ---------------------------------------------------------------------------
__global__ __launch_bounds__(256)
void gather_kernel(const float* __restrict__ x,
                   const float* __restrict__ eps_p,
                   float* __restrict__ h0, int n_nodes) {
    int warp = (blockIdx.x * blockDim.x + threadIdx.x) >> 5;
    if (warp >= n_nodes) return;
    int lane = threadIdx.x & 31;

    int cnt_full = __ldg(&g_cnt[warp]);
    int cnt = min(cnt_full, CAP);
    float s = 1.0f + __ldg(eps_p);

    const float4* x4 = (const float4*)x;
    float4 v = __ldg(x4 + (size_t)warp * 32 + lane);
    float4 acc = make_float4(v.x * s, v.y * s, v.z * s, v.w * s);

    const int* slots = g_slot + (size_t)warp * CAP;
    for (int b = 0; b < cnt; b += 32) {
        int c = min(32, cnt - b);
        int idx = (lane < c) ? __ldg(slots + b + lane) : 0;
#pragma unroll 4
        for (int j = 0; j < c; j++) {
            int sj = __shfl_sync(0xffffffffu, idx, j);
            float4 w = __ldg(x4 + (size_t)sj * 32 + lane);
            acc.x += w.x; acc.y += w.y; acc.z += w.z; acc.w += w.w;
        }
    }
    if (cnt_full > CAP) {   // exact overflow path (empty in practice)
        int n = g_ovf_n;
        for (int e = 0; e < n; e++) {
            int2 sd = g_ovf[e];
            if (sd.y == warp) {
                float4 w = __ldg(x4 + (size_t)sd.x * 32 + lane);
                acc.x += w.x; acc.y += w.y; acc.z += w.z; acc.w += w.w;
            }
        }
    }
    ((float4*)h0)[(size_t)warp * 32 + lane] = acc;
}

// ---------------------------------------------------------------------------
// mma.sync tf32 helpers (portable HMMA; tcgen05 fenced off by base sm_103)
// ---------------------------------------------------------------------------
__device__ __forceinline__ uint32_t f2tf32(float f) {
    uint32_t r;
    asm("cvt.rna.tf32.f32 %0, %1;" : "=r"(r) : "f"(f));
    return r;
}
__device__ __forceinline__ void mma_tf32(float* c, const uint32_t* a, const uint32_t* b) {
    asm volatile(
        "mma.sync.aligned.m16n8k8.row.col.f32.tf32.tf32.f32 "
        "{%0,%1,%2,%3}, {%4,%5,%6,%7}, {%8,%9}, {%0,%1,%2,%3};"
        : "+f"(c[0]), "+f"(c[1]), "+f"(c[2]), "+f"(c[3])
        : "r"(a[0]), "r"(a[1]), "r"(a[2]), "r"(a[3]),
          "r"(b[0]), "r"(b[1]));
}

#define LDS_STRIDE 132

// ---------------------------------------------------------------------------
// Kernel 4: fused MLP. out = relu(h0@W1t^T + b1) @ W2t^T + b2.
// Both weight tiles preloaded upfront (Bs1, Bs2); relu tile written back
// into As between mainloops. 198 KB dynamic smem, 1 CTA/SM.
// ---------------------------------------------------------------------------
__global__ __launch_bounds__(256, 1)
void fused_mlp_kernel(const float* __restrict__ A,
                      const float* __restrict__ W1t,
                      const float* __restrict__ b1,
                      const float* __restrict__ W2t,
                      const float* __restrict__ b2,
                      float* __restrict__ C, int M) {
    extern __shared__ float smem[];
    float* As  = smem;                          // [128][132]
    float* Bs1 = smem + 128 * LDS_STRIDE;       // [128][132] (W1t, [n][k])
    float* Bs2 = smem + 2 * 128 * LDS_STRIDE;   // [128][132] (W2t, [n][k])

    const int tid = threadIdx.x;
    const int wid = tid >> 5;
    const int lid = tid & 31;
    const int wm = wid >> 2;
    const int wn = wid & 3;
    const int gid = lid >> 2;
    const int tig = lid & 3;
    const int row0 = blockIdx.x * 128;

    // ---- load A tile + W1 + W2 (tf32-round at store time) ----
#pragma unroll
    for (int it = 0; it < 16; it++) {
        int idx = tid + it * 256;
        int r = idx >> 5;
        int c4 = idx & 31;
        float4 va = make_float4(0.f, 0.f, 0.f, 0.f);
        int grow = row0 + r;
        if (grow < M) va = __ldg((const float4*)(A + (size_t)grow * 128) + c4);
        uint32_t* ap = (uint32_t*)&As[r * LDS_STRIDE + c4 * 4];
        ap[0] = f2tf32(va.x); ap[1] = f2tf32(va.y);
        ap[2] = f2tf32(va.z); ap[3] = f2tf32(va.w);

        float4 v1 = __ldg((const float4*)(W1t + (size_t)r * 128) + c4);
        uint32_t* p1 = (uint32_t*)&Bs1[r * LDS_STRIDE + c4 * 4];
        p1[0] = f2tf32(v1.x); p1[1] = f2tf32(v1.y);
        p1[2] = f2tf32(v1.z); p1[3] = f2tf32(v1.w);

        float4 v2 = __ldg((const float4*)(W2t + (size_t)r * 128) + c4);
        uint32_t* p2 = (uint32_t*)&Bs2[r * LDS_STRIDE + c4 * 4];
        p2[0] = f2tf32(v2.x); p2[1] = f2tf32(v2.y);
        p2[2] = f2tf32(v2.z); p2[3] = f2tf32(v2.w);
    }
    __syncthreads();

    float acc[4][4][4];
#pragma unroll
    for (int mt = 0; mt < 4; mt++)
#pragma unroll
        for (int nt = 0; nt < 4; nt++)
#pragma unroll
            for (int q = 0; q < 4; q++) acc[mt][nt][q] = 0.0f;

    // ---- mainloop 1 (Bs1) ----
#pragma unroll
    for (int k0 = 0; k0 < 128; k0 += 8) {
        uint32_t bfr[4][2];
#pragma unroll
        for (int nt = 0; nt < 4; nt++) {
            const uint32_t* bp = (const uint32_t*)
                &Bs1[(wn * 32 + nt * 8 + gid) * LDS_STRIDE + k0 + tig];
            bfr[nt][0] = bp[0];
            bfr[nt][1] = bp[4];
        }
#pragma unroll
        for (int mt = 0; mt < 4; mt++) {
            uint32_t afr[4];
            const uint32_t* ap = (const uint32_t*)
                &As[(wm * 64 + mt * 16 + gid) * LDS_STRIDE + k0 + tig];
            afr[0] = ap[0];
            afr[1] = ap[8 * LDS_STRIDE];
            afr[2] = ap[4];
            afr[3] = ap[8 * LDS_STRIDE + 4];
#pragma unroll
            for (int nt = 0; nt < 4; nt++)
                mma_tf32(acc[mt][nt], afr, bfr[nt]);
        }
    }
    __syncthreads();   // all As reads done before overwrite

    // ---- relu(acc + b1) back into As (tf32) ----
#pragma unroll
    for (int mt = 0; mt < 4; mt++) {
        int r0 = wm * 64 + mt * 16 + gid;
#pragma unroll
        for (int nt = 0; nt < 4; nt++) {
            int c0 = wn * 32 + nt * 8 + 2 * tig;
            float bb0 = __ldg(b1 + c0), bb1 = __ldg(b1 + c0 + 1);
            uint32_t* p0 = (uint32_t*)&As[r0 * LDS_STRIDE + c0];
            uint32_t* p1 = (uint32_t*)&As[(r0 + 8) * LDS_STRIDE + c0];
            p0[0] = f2tf32(fmaxf(acc[mt][nt][0] + bb0, 0.f));
            p0[1] = f2tf32(fmaxf(acc[mt][nt][1] + bb1, 0.f));
            p1[0] = f2tf32(fmaxf(acc[mt][nt][2] + bb0, 0.f));
            p1[1] = f2tf32(fmaxf(acc[mt][nt][3] + bb1, 0.f));
        }
    }
    __syncthreads();

    // ---- mainloop 2 (Bs2) ----
#pragma unroll
    for (int mt = 0; mt < 4; mt++)
#pragma unroll
        for (int nt = 0; nt < 4; nt++)
#pragma unroll
            for (int q = 0; q < 4; q++) acc[mt][nt][q] = 0.0f;

#pragma unroll
    for (int k0 = 0; k0 < 128; k0 += 8) {
        uint32_t bfr[4][2];
#pragma unroll
        for (int nt = 0; nt < 4; nt++) {
            const uint32_t* bp = (const uint32_t*)
                &Bs2[(wn * 32 + nt * 8 + gid) * LDS_STRIDE + k0 + tig];
            bfr[nt][0] = bp[0];
            bfr[nt][1] = bp[4];
        }
#pragma unroll
        for (int mt = 0; mt < 4; mt++) {
            uint32_t afr[4];
            const uint32_t* ap = (const uint32_t*)
                &As[(wm * 64 + mt * 16 + gid) * LDS_STRIDE + k0 + tig];
            afr[0] = ap[0];
            afr[1] = ap[8 * LDS_STRIDE];
            afr[2] = ap[4];
            afr[3] = ap[8 * LDS_STRIDE + 4];
#pragma unroll
            for (int nt = 0; nt < 4; nt++)
                mma_tf32(acc[mt][nt], afr, bfr[nt]);
        }
    }

    // ---- epilogue to global ----
#pragma unroll
    for (int mt = 0; mt < 4; mt++) {
        int r0 = row0 + wm * 64 + mt * 16 + gid;
        int r1 = r0 + 8;
#pragma unroll
        for (int nt = 0; nt < 4; nt++) {
            int c0 = wn * 32 + nt * 8 + 2 * tig;
            float bb0 = __ldg(b2 + c0), bb1 = __ldg(b2 + c0 + 1);
            float2 v0 = make_float2(acc[mt][nt][0] + bb0, acc[mt][nt][1] + bb1);
            float2 v1 = make_float2(acc[mt][nt][2] + bb0, acc[mt][nt][3] + bb1);
            if (r0 < M) *(float2*)(C + (size_t)r0 * 128 + c0) = v0;
            if (r1 < M) *(float2*)(C + (size_t)r1 * 128 + c0) = v1;
        }
    }
}

// ---------------------------------------------------------------------------
extern "C" void kernel_launch(void* const* d_in, const int* in_sizes, int n_in,
                              void* d_out, int out_size) {
    const float* x   = (const float*)d_in[0];
    const int*   ei  = (const int*)d_in[1];
    const float* W1  = (const float*)d_in[2];
    const float* b1  = (const float*)d_in[3];
    const float* W2  = (const float*)d_in[4];
    const float* b2  = (const float*)d_in[5];
    const float* eps = (const float*)d_in[6];
    float*       out = (float*)d_out;

    const int n_nodes = in_sizes[0] / D;
    const int n_edges = in_sizes[1] / 2;
    const int* src = ei;
    const int* dst = ei + n_edges;

    float *h0, *w1t, *w2t;
    cudaGetSymbolAddress((void**)&h0, g_h0);
    cudaGetSymbolAddress((void**)&w1t, g_W1t);
    cudaGetSymbolAddress((void**)&w2t, g_W2t);

    const int SMEM = 3 * 128 * LDS_STRIDE * (int)sizeof(float);  // 202752
    cudaFuncSetAttribute(fused_mlp_kernel,
                         cudaFuncAttributeMaxDynamicSharedMemorySize, SMEM);

    zero_kernel<<<(n_nodes + 255) / 256, 256>>>(n_nodes);

    int n_fill = (n_edges + 255) / 256;
    fill_kernel<<<n_fill + 32, 256>>>(src, dst, n_edges, n_fill,
                                      W1, w1t, W2, w2t);

    int gwarps = (n_nodes * 32 + 255) / 256;
    gather_kernel<<<gwarps, 256>>>(x, eps, h0, n_nodes);

    int gblocks = (n_nodes + 127) / 128;
    fused_mlp_kernel<<<gblocks, 256, SMEM>>>(h0, w1t, b1, w2t, b2, out, n_nodes);
}

// round 7
// speedup vs baseline: 2.6471x; 1.0270x over previous
#include <cuda_runtime.h>
#include <cstdint>

#define NN  100000
#define NE  1600000
#define D   128
#define CAP 64   // slots per node; overflow handled exactly via side list

__device__ float g_h0[(size_t)NN * D];
__device__ float g_W1t[D * D];
__device__ float g_W2t[D * D];
__device__ int   g_cnt[NN];
__device__ int   g_slot[(size_t)NN * CAP];
__device__ int   g_ovf_n;
__device__ int2  g_ovf[NE];

// ---------------------------------------------------------------------------
// Kernel 1: zero counters (graph replays -> must reset every call)
// ---------------------------------------------------------------------------
__global__ void zero_kernel(int n) {
    int i = blockIdx.x * blockDim.x + threadIdx.x;
    if (i < n) g_cnt[i] = 0;
    if (i == 0) g_ovf_n = 0;
}

// ---------------------------------------------------------------------------
// Kernel 2: binned fill (blocks [0, n_fill)) + weight transposes (32 tail
// blocks).
// ---------------------------------------------------------------------------
__global__ __launch_bounds__(256)
void fill_kernel(const int* __restrict__ src,
                 const int* __restrict__ dst, int n_edges, int n_fill,
                 const float* __restrict__ W1, float* __restrict__ W1t,
                 const float* __restrict__ W2, float* __restrict__ W2t) {
    __shared__ float t[32][33];
    if (blockIdx.x >= n_fill) {
        int bid = blockIdx.x - n_fill;        // 0..31
        const float* W  = (bid & 16) ? W2 : W1;
        float*       Wt = (bid & 16) ? W2t : W1t;
        int bx = (bid & 3) * 32, by = ((bid >> 2) & 3) * 32;
        int x = threadIdx.x & 31, y = threadIdx.x >> 5;   // (32,8)
#pragma unroll
        for (int i = 0; i < 32; i += 8)
            t[y + i][x] = W[(size_t)(by + y + i) * D + bx + x];
        __syncthreads();
#pragma unroll
        for (int i = 0; i < 32; i += 8)
            Wt[(size_t)(bx + y + i) * D + by + x] = t[x][y + i];
        return;
    }
    int e = blockIdx.x * blockDim.x + threadIdx.x;
    if (e >= n_edges) return;
    int s = __ldg(src + e);
    int d = __ldg(dst + e);
    int p = atomicAdd(&g_cnt[d], 1);
    if (p < CAP) {
        g_slot[(size_t)d * CAP + p] = s;
    } else {
        int q = atomicAdd(&g_ovf_n, 1);
        g_ovf[q] = make_int2(s, d);
    }
}

// ---------------------------------------------------------------------------
// Kernel 3: gather. One warp per node (at the LTS roofline).
// ---------------------------------------------------------------------------
__global__ __launch_bounds__(256)
void gather_kernel(const float* __restrict__ x,
                   const float* __restrict__ eps_p,
                   float* __restrict__ h0, int n_nodes) {
    int warp = (blockIdx.x * blockDim.x + threadIdx.x) >> 5;
    if (warp >= n_nodes) return;
    int lane = threadIdx.x & 31;

    int cnt_full = __ldg(&g_cnt[warp]);
    int cnt = min(cnt_full, CAP);
    float s = 1.0f + __ldg(eps_p);

    const float4* x4 = (const float4*)x;
    float4 v = __ldg(x4 + (size_t)warp * 32 + lane);
    float4 acc = make_float4(v.x * s, v.y * s, v.z * s, v.w * s);

    const int* slots = g_slot + (size_t)warp * CAP;
    for (int b = 0; b < cnt; b += 32) {
        int c = min(32, cnt - b);
        int idx = (lane < c) ? __ldg(slots + b + lane) : 0;
#pragma unroll 4
        for (int j = 0; j < c; j++) {
            int sj = __shfl_sync(0xffffffffu, idx, j);
            float4 w = __ldg(x4 + (size_t)sj * 32 + lane);
            acc.x += w.x; acc.y += w.y; acc.z += w.z; acc.w += w.w;
        }
    }
    if (cnt_full > CAP) {   // exact overflow path (empty in practice)
        int n = g_ovf_n;
        for (int e = 0; e < n; e++) {
            int2 sd = g_ovf[e];
            if (sd.y == warp) {
                float4 w = __ldg(x4 + (size_t)sd.x * 32 + lane);
                acc.x += w.x; acc.y += w.y; acc.z += w.z; acc.w += w.w;
            }
        }
    }
    ((float4*)h0)[(size_t)warp * 32 + lane] = acc;
}

// ---------------------------------------------------------------------------
// mma.sync tf32 helpers
// ---------------------------------------------------------------------------
__device__ __forceinline__ uint32_t f2tf32(float f) {
    uint32_t r;
    asm("cvt.rna.tf32.f32 %0, %1;" : "=r"(r) : "f"(f));
    return r;
}
__device__ __forceinline__ void mma_tf32(float* c, const uint32_t* a, const uint32_t* b) {
    asm volatile(
        "mma.sync.aligned.m16n8k8.row.col.f32.tf32.tf32.f32 "
        "{%0,%1,%2,%3}, {%4,%5,%6,%7}, {%8,%9}, {%0,%1,%2,%3};"
        : "+f"(c[0]), "+f"(c[1]), "+f"(c[2]), "+f"(c[3])
        : "r"(a[0]), "r"(a[1]), "r"(a[2]), "r"(a[3]),
          "r"(b[0]), "r"(b[1]));
}

#define LDS_STRIDE 132

// ---------------------------------------------------------------------------
// Kernel 4: fused MLP, 64-row tile, 2 CTAs/SM.
// SMEM: As[64][132] + Bs[128][132] = 101 KB. Bs holds W1 then W2 (reload).
// Warp grid 2(M)x4(N): warp tile 32x32, acc[2][4][4] (32 regs).
// ---------------------------------------------------------------------------
__global__ __launch_bounds__(256, 2)
void fused_mlp_kernel(const float* __restrict__ A,
                      const float* __restrict__ W1t,
                      const float* __restrict__ b1,
                      const float* __restrict__ W2t,
                      const float* __restrict__ b2,
                      float* __restrict__ C, int M) {
    extern __shared__ float smem[];
    float* As = smem;                       // [64][132]
    float* Bs = smem + 64 * LDS_STRIDE;     // [128][132] (weights, [n][k])

    const int tid = threadIdx.x;
    const int wid = tid >> 5;
    const int lid = tid & 31;
    const int wm = wid >> 2;            // 0..1 -> 32-row slab
    const int wn = wid & 3;             // 0..3 -> 32-col slab
    const int gid = lid >> 2;
    const int tig = lid & 3;
    const int row0 = blockIdx.x * 64;

    // ---- load A tile (64 rows) + W1 ----
#pragma unroll
    for (int it = 0; it < 8; it++) {
        int idx = tid + it * 256;          // 0..2047
        int r = idx >> 5;
        int c4 = idx & 31;
        float4 va = make_float4(0.f, 0.f, 0.f, 0.f);
        int grow = row0 + r;
        if (grow < M) va = __ldg((const float4*)(A + (size_t)grow * 128) + c4);
        uint32_t* ap = (uint32_t*)&As[r * LDS_STRIDE + c4 * 4];
        ap[0] = f2tf32(va.x); ap[1] = f2tf32(va.y);
        ap[2] = f2tf32(va.z); ap[3] = f2tf32(va.w);
    }
#pragma unroll
    for (int it = 0; it < 16; it++) {
        int idx = tid + it * 256;          // 0..4095
        int r = idx >> 5;
        int c4 = idx & 31;
        float4 vb = __ldg((const float4*)(W1t + (size_t)r * 128) + c4);
        uint32_t* bp = (uint32_t*)&Bs[r * LDS_STRIDE + c4 * 4];
        bp[0] = f2tf32(vb.x); bp[1] = f2tf32(vb.y);
        bp[2] = f2tf32(vb.z); bp[3] = f2tf32(vb.w);
    }
    __syncthreads();

    float acc[2][4][4];
#pragma unroll
    for (int mt = 0; mt < 2; mt++)
#pragma unroll
        for (int nt = 0; nt < 4; nt++)
#pragma unroll
            for (int q = 0; q < 4; q++) acc[mt][nt][q] = 0.0f;

    // ---- mainloop 1 (W1) ----
#pragma unroll
    for (int k0 = 0; k0 < 128; k0 += 8) {
        uint32_t bfr[4][2];
#pragma unroll
        for (int nt = 0; nt < 4; nt++) {
            const uint32_t* bp = (const uint32_t*)
                &Bs[(wn * 32 + nt * 8 + gid) * LDS_STRIDE + k0 + tig];
            bfr[nt][0] = bp[0];
            bfr[nt][1] = bp[4];
        }
#pragma unroll
        for (int mt = 0; mt < 2; mt++) {
            uint32_t afr[4];
            const uint32_t* ap = (const uint32_t*)
                &As[(wm * 32 + mt * 16 + gid) * LDS_STRIDE + k0 + tig];
            afr[0] = ap[0];
            afr[1] = ap[8 * LDS_STRIDE];
            afr[2] = ap[4];
            afr[3] = ap[8 * LDS_STRIDE + 4];
#pragma unroll
            for (int nt = 0; nt < 4; nt++)
                mma_tf32(acc[mt][nt], afr, bfr[nt]);
        }
    }
    __syncthreads();   // all As/Bs reads done before overwrite

    // ---- relu(acc + b1) back into As (tf32) ----
#pragma unroll
    for (int mt = 0; mt < 2; mt++) {
        int r0 = wm * 32 + mt * 16 + gid;
#pragma unroll
        for (int nt = 0; nt < 4; nt++) {
            int c0 = wn * 32 + nt * 8 + 2 * tig;
            float bb0 = __ldg(b1 + c0), bb1 = __ldg(b1 + c0 + 1);
            uint32_t* p0 = (uint32_t*)&As[r0 * LDS_STRIDE + c0];
            uint32_t* p1 = (uint32_t*)&As[(r0 + 8) * LDS_STRIDE + c0];
            p0[0] = f2tf32(fmaxf(acc[mt][nt][0] + bb0, 0.f));
            p0[1] = f2tf32(fmaxf(acc[mt][nt][1] + bb1, 0.f));
            p1[0] = f2tf32(fmaxf(acc[mt][nt][2] + bb0, 0.f));
            p1[1] = f2tf32(fmaxf(acc[mt][nt][3] + bb1, 0.f));
        }
    }
    // ---- reload Bs = W2 ----
#pragma unroll
    for (int it = 0; it < 16; it++) {
        int idx = tid + it * 256;
        int r = idx >> 5;
        int c4 = idx & 31;
        float4 vb = __ldg((const float4*)(W2t + (size_t)r * 128) + c4);
        uint32_t* bp = (uint32_t*)&Bs[r * LDS_STRIDE + c4 * 4];
        bp[0] = f2tf32(vb.x); bp[1] = f2tf32(vb.y);
        bp[2] = f2tf32(vb.z); bp[3] = f2tf32(vb.w);
    }
    __syncthreads();

    // ---- mainloop 2 (W2) ----
#pragma unroll
    for (int mt = 0; mt < 2; mt++)
#pragma unroll
        for (int nt = 0; nt < 4; nt++)
#pragma unroll
            for (int q = 0; q < 4; q++) acc[mt][nt][q] = 0.0f;

#pragma unroll
    for (int k0 = 0; k0 < 128; k0 += 8) {
        uint32_t bfr[4][2];
#pragma unroll
        for (int nt = 0; nt < 4; nt++) {
            const uint32_t* bp = (const uint32_t*)
                &Bs[(wn * 32 + nt * 8 + gid) * LDS_STRIDE + k0 + tig];
            bfr[nt][0] = bp[0];
            bfr[nt][1] = bp[4];
        }
#pragma unroll
        for (int mt = 0; mt < 2; mt++) {
            uint32_t afr[4];
            const uint32_t* ap = (const uint32_t*)
                &As[(wm * 32 + mt * 16 + gid) * LDS_STRIDE + k0 + tig];
            afr[0] = ap[0];
            afr[1] = ap[8 * LDS_STRIDE];
            afr[2] = ap[4];
            afr[3] = ap[8 * LDS_STRIDE + 4];
#pragma unroll
            for (int nt = 0; nt < 4; nt++)
                mma_tf32(acc[mt][nt], afr, bfr[nt]);
        }
    }

    // ---- epilogue to global ----
#pragma unroll
    for (int mt = 0; mt < 2; mt++) {
        int r0 = row0 + wm * 32 + mt * 16 + gid;
        int r1 = r0 + 8;
#pragma unroll
        for (int nt = 0; nt < 4; nt++) {
            int c0 = wn * 32 + nt * 8 + 2 * tig;
            float bb0 = __ldg(b2 + c0), bb1 = __ldg(b2 + c0 + 1);
            float2 v0 = make_float2(acc[mt][nt][0] + bb0, acc[mt][nt][1] + bb1);
            float2 v1 = make_float2(acc[mt][nt][2] + bb0, acc[mt][nt][3] + bb1);
            if (r0 < M) *(float2*)(C + (size_t)r0 * 128 + c0) = v0;
            if (r1 < M) *(float2*)(C + (size_t)r1 * 128 + c0) = v1;
        }
    }
}

// ---------------------------------------------------------------------------
extern "C" void kernel_launch(void* const* d_in, const int* in_sizes, int n_in,
                              void* d_out, int out_size) {
    const float* x   = (const float*)d_in[0];
    const int*   ei  = (const int*)d_in[1];
    const float* W1  = (const float*)d_in[2];
    const float* b1  = (const float*)d_in[3];
    const float* W2  = (const float*)d_in[4];
    const float* b2  = (const float*)d_in[5];
    const float* eps = (const float*)d_in[6];
    float*       out = (float*)d_out;

    const int n_nodes = in_sizes[0] / D;
    const int n_edges = in_sizes[1] / 2;
    const int* src = ei;
    const int* dst = ei + n_edges;

    float *h0, *w1t, *w2t;
    cudaGetSymbolAddress((void**)&h0, g_h0);
    cudaGetSymbolAddress((void**)&w1t, g_W1t);
    cudaGetSymbolAddress((void**)&w2t, g_W2t);

    const int SMEM = (64 + 128) * LDS_STRIDE * (int)sizeof(float);  // 101376
    cudaFuncSetAttribute(fused_mlp_kernel,
                         cudaFuncAttributeMaxDynamicSharedMemorySize, SMEM);

    zero_kernel<<<(n_nodes + 255) / 256, 256>>>(n_nodes);

    int n_fill = (n_edges + 255) / 256;
    fill_kernel<<<n_fill + 32, 256>>>(src, dst, n_edges, n_fill,
                                      W1, w1t, W2, w2t);

    int gwarps = (n_nodes * 32 + 255) / 256;
    gather_kernel<<<gwarps, 256>>>(x, eps, h0, n_nodes);

    int gblocks = (n_nodes + 63) / 64;
    fused_mlp_kernel<<<gblocks, 256, SMEM>>>(h0, w1t, b1, w2t, b2, out, n_nodes);
}

// round 8
// speedup vs baseline: 2.8017x; 1.0584x over previous
#include <cuda_runtime.h>
#include <cstdint>

#define NN  100000
#define NE  1600000
#define D   128
#define CAP 64   // slots per node; overflow handled exactly via side list

__device__ float g_h0[(size_t)NN * D];
__device__ float g_W1t[D * D];
__device__ float g_W2t[D * D];
__device__ int   g_cnt[NN];
__device__ int   g_slot[(size_t)NN * CAP];
__device__ int   g_ovf_n;
__device__ int2  g_ovf[NE];

// ---------------------------------------------------------------------------
// Kernel 1: zero counters (graph replays -> must reset every call)
// ---------------------------------------------------------------------------
__global__ void zero_kernel(int n) {
    int i = blockIdx.x * blockDim.x + threadIdx.x;
    if (i < n) g_cnt[i] = 0;
    if (i == 0) g_ovf_n = 0;
}

// ---------------------------------------------------------------------------
// Kernel 2: binned fill + weight transposes (32 tail blocks)
// ---------------------------------------------------------------------------
__global__ __launch_bounds__(256)
void fill_kernel(const int* __restrict__ src,
                 const int* __restrict__ dst, int n_edges, int n_fill,
                 const float* __restrict__ W1, float* __restrict__ W1t,
                 const float* __restrict__ W2, float* __restrict__ W2t) {
    __shared__ float t[32][33];
    if (blockIdx.x >= n_fill) {
        int bid = blockIdx.x - n_fill;        // 0..31
        const float* W  = (bid & 16) ? W2 : W1;
        float*       Wt = (bid & 16) ? W2t : W1t;
        int bx = (bid & 3) * 32, by = ((bid >> 2) & 3) * 32;
        int x = threadIdx.x & 31, y = threadIdx.x >> 5;   // (32,8)
#pragma unroll
        for (int i = 0; i < 32; i += 8)
            t[y + i][x] = W[(size_t)(by + y + i) * D + bx + x];
        __syncthreads();
#pragma unroll
        for (int i = 0; i < 32; i += 8)
            Wt[(size_t)(bx + y + i) * D + by + x] = t[x][y + i];
        return;
    }
    int e = blockIdx.x * blockDim.x + threadIdx.x;
    if (e >= n_edges) return;
    int s = __ldg(src + e);
    int d = __ldg(dst + e);
    int p = atomicAdd(&g_cnt[d], 1);
    if (p < CAP) {
        g_slot[(size_t)d * CAP + p] = s;
    } else {
        int q = atomicAdd(&g_ovf_n, 1);
        g_ovf[q] = make_int2(s, d);
    }
}

// ---------------------------------------------------------------------------
// Kernel 3: gather. One warp per node (at the LTS roofline).
// ---------------------------------------------------------------------------
__global__ __launch_bounds__(256)
void gather_kernel(const float* __restrict__ x,
                   const float* __restrict__ eps_p,
                   float* __restrict__ h0, int n_nodes) {
    int warp = (blockIdx.x * blockDim.x + threadIdx.x) >> 5;
    if (warp >= n_nodes) return;
    int lane = threadIdx.x & 31;

    int cnt_full = __ldg(&g_cnt[warp]);
    int cnt = min(cnt_full, CAP);
    float s = 1.0f + __ldg(eps_p);

    const float4* x4 = (const float4*)x;
    float4 v = __ldg(x4 + (size_t)warp * 32 + lane);
    float4 acc = make_float4(v.x * s, v.y * s, v.z * s, v.w * s);

    const int* slots = g_slot + (size_t)warp * CAP;
    for (int b = 0; b < cnt; b += 32) {
        int c = min(32, cnt - b);
        int idx = (lane < c) ? __ldg(slots + b + lane) : 0;
#pragma unroll 4
        for (int j = 0; j < c; j++) {
            int sj = __shfl_sync(0xffffffffu, idx, j);
            float4 w = __ldg(x4 + (size_t)sj * 32 + lane);
            acc.x += w.x; acc.y += w.y; acc.z += w.z; acc.w += w.w;
        }
    }
    if (cnt_full > CAP) {   // exact overflow path (empty in practice)
        int n = g_ovf_n;
        for (int e = 0; e < n; e++) {
            int2 sd = g_ovf[e];
            if (sd.y == warp) {
                float4 w = __ldg(x4 + (size_t)sd.x * 32 + lane);
                acc.x += w.x; acc.y += w.y; acc.z += w.z; acc.w += w.w;
            }
        }
    }
    ((float4*)h0)[(size_t)warp * 32 + lane] = acc;
}

// ---------------------------------------------------------------------------
// mma.sync tf32 helpers
// ---------------------------------------------------------------------------
__device__ __forceinline__ uint32_t f2tf32(float f) {
    uint32_t r;
    asm("cvt.rna.tf32.f32 %0, %1;" : "=r"(r) : "f"(f));
    return r;
}
__device__ __forceinline__ void mma_tf32(float* c, const uint32_t* a, const uint32_t* b) {
    asm volatile(
        "mma.sync.aligned.m16n8k8.row.col.f32.tf32.tf32.f32 "
        "{%0,%1,%2,%3}, {%4,%5,%6,%7}, {%8,%9}, {%0,%1,%2,%3};"
        : "+f"(c[0]), "+f"(c[1]), "+f"(c[2]), "+f"(c[3])
        : "r"(a[0]), "r"(a[1]), "r"(a[2]), "r"(a[3]),
          "r"(b[0]), "r"(b[1]));
}

#define LDS_STRIDE 132
#define TM 256   // CTA rows

// ---------------------------------------------------------------------------
// Kernel 4: fused MLP. CTA tile 256x128, 8 warps in 4(M)x2(N), warp tile
// 64x64 -> 128 B of LDS per MMA (crossbar-byte relief). SMEM: As[256][132] +
// Bs[128][132] = 203 KB, 1 CTA/SM. Bs holds W1 then W2 (mid reload).
// ---------------------------------------------------------------------------
__global__ __launch_bounds__(256, 1)
void fused_mlp_kernel(const float* __restrict__ A,
                      const float* __restrict__ W1t,
                      const float* __restrict__ b1,
                      const float* __restrict__ W2t,
                      const float* __restrict__ b2,
                      float* __restrict__ C, int M) {
    extern __shared__ float smem[];
    float* As = smem;                       // [256][132]
    float* Bs = smem + TM * LDS_STRIDE;     // [128][132] (weights, [n][k])

    const int tid = threadIdx.x;
    const int wid = tid >> 5;
    const int lid = tid & 31;
    const int wm = wid >> 1;            // 0..3 -> 64-row slab
    const int wn = wid & 1;             // 0..1 -> 64-col slab
    const int gid = lid >> 2;
    const int tig = lid & 3;
    const int row0 = blockIdx.x * TM;

    // ---- load A tile (256 rows) ----
#pragma unroll
    for (int it = 0; it < 32; it++) {
        int idx = tid + it * 256;          // 0..8191
        int r = idx >> 5;
        int c4 = idx & 31;
        float4 va = make_float4(0.f, 0.f, 0.f, 0.f);
        int grow = row0 + r;
        if (grow < M) va = __ldg((const float4*)(A + (size_t)grow * 128) + c4);
        uint32_t* ap = (uint32_t*)&As[r * LDS_STRIDE + c4 * 4];
        ap[0] = f2tf32(va.x); ap[1] = f2tf32(va.y);
        ap[2] = f2tf32(va.z); ap[3] = f2tf32(va.w);
    }
    // ---- load W1 ----
#pragma unroll
    for (int it = 0; it < 16; it++) {
        int idx = tid + it * 256;          // 0..4095
        int r = idx >> 5;
        int c4 = idx & 31;
        float4 vb = __ldg((const float4*)(W1t + (size_t)r * 128) + c4);
        uint32_t* bp = (uint32_t*)&Bs[r * LDS_STRIDE + c4 * 4];
        bp[0] = f2tf32(vb.x); bp[1] = f2tf32(vb.y);
        bp[2] = f2tf32(vb.z); bp[3] = f2tf32(vb.w);
    }
    __syncthreads();

    float acc[4][8][4];
#pragma unroll
    for (int mt = 0; mt < 4; mt++)
#pragma unroll
        for (int nt = 0; nt < 8; nt++)
#pragma unroll
            for (int q = 0; q < 4; q++) acc[mt][nt][q] = 0.0f;

    // ---- mainloop 1 (W1) ----
#pragma unroll 4
    for (int k0 = 0; k0 < 128; k0 += 8) {
        uint32_t bfr[8][2];
#pragma unroll
        for (int nt = 0; nt < 8; nt++) {
            const uint32_t* bp = (const uint32_t*)
                &Bs[(wn * 64 + nt * 8 + gid) * LDS_STRIDE + k0 + tig];
            bfr[nt][0] = bp[0];
            bfr[nt][1] = bp[4];
        }
#pragma unroll
        for (int mt = 0; mt < 4; mt++) {
            uint32_t afr[4];
            const uint32_t* ap = (const uint32_t*)
                &As[(wm * 64 + mt * 16 + gid) * LDS_STRIDE + k0 + tig];
            afr[0] = ap[0];
            afr[1] = ap[8 * LDS_STRIDE];
            afr[2] = ap[4];
            afr[3] = ap[8 * LDS_STRIDE + 4];
#pragma unroll
            for (int nt = 0; nt < 8; nt++)
                mma_tf32(acc[mt][nt], afr, bfr[nt]);
        }
    }
    __syncthreads();   // all As/Bs reads done before overwrite

    // ---- relu(acc + b1) back into As (tf32, STS.64) ----
#pragma unroll
    for (int mt = 0; mt < 4; mt++) {
        int r0 = wm * 64 + mt * 16 + gid;
#pragma unroll
        for (int nt = 0; nt < 8; nt++) {
            int c0 = wn * 64 + nt * 8 + 2 * tig;
            float bb0 = __ldg(b1 + c0), bb1 = __ldg(b1 + c0 + 1);
            uint2 v0, v1;
            v0.x = f2tf32(fmaxf(acc[mt][nt][0] + bb0, 0.f));
            v0.y = f2tf32(fmaxf(acc[mt][nt][1] + bb1, 0.f));
            v1.x = f2tf32(fmaxf(acc[mt][nt][2] + bb0, 0.f));
            v1.y = f2tf32(fmaxf(acc[mt][nt][3] + bb1, 0.f));
            *(uint2*)&As[r0 * LDS_STRIDE + c0] = v0;
            *(uint2*)&As[(r0 + 8) * LDS_STRIDE + c0] = v1;
        }
    }
    // ---- reload Bs = W2 ----
#pragma unroll
    for (int it = 0; it < 16; it++) {
        int idx = tid + it * 256;
        int r = idx >> 5;
        int c4 = idx & 31;
        float4 vb = __ldg((const float4*)(W2t + (size_t)r * 128) + c4);
        uint32_t* bp = (uint32_t*)&Bs[r * LDS_STRIDE + c4 * 4];
        bp[0] = f2tf32(vb.x); bp[1] = f2tf32(vb.y);
        bp[2] = f2tf32(vb.z); bp[3] = f2tf32(vb.w);
    }
    __syncthreads();

    // ---- mainloop 2 (W2) ----
#pragma unroll
    for (int mt = 0; mt < 4; mt++)
#pragma unroll
        for (int nt = 0; nt < 8; nt++)
#pragma unroll
            for (int q = 0; q < 4; q++) acc[mt][nt][q] = 0.0f;

#pragma unroll 4
    for (int k0 = 0; k0 < 128; k0 += 8) {
        uint32_t bfr[8][2];
#pragma unroll
        for (int nt = 0; nt < 8; nt++) {
            const uint32_t* bp = (const uint32_t*)
                &Bs[(wn * 64 + nt * 8 + gid) * LDS_STRIDE + k0 + tig];
            bfr[nt][0] = bp[0];
            bfr[nt][1] = bp[4];
        }
#pragma unroll
        for (int mt = 0; mt < 4; mt++) {
            uint32_t afr[4];
            const uint32_t* ap = (const uint32_t*)
                &As[(wm * 64 + mt * 16 + gid) * LDS_STRIDE + k0 + tig];
            afr[0] = ap[0];
            afr[1] = ap[8 * LDS_STRIDE];
            afr[2] = ap[4];
            afr[3] = ap[8 * LDS_STRIDE + 4];
#pragma unroll
            for (int nt = 0; nt < 8; nt++)
                mma_tf32(acc[mt][nt], afr, bfr[nt]);
        }
    }

    // ---- epilogue to global ----
#pragma unroll
    for (int mt = 0; mt < 4; mt++) {
        int r0 = row0 + wm * 64 + mt * 16 + gid;
        int r1 = r0 + 8;
#pragma unroll
        for (int nt = 0; nt < 8; nt++) {
            int c0 = wn * 64 + nt * 8 + 2 * tig;
            float bb0 = __ldg(b2 + c0), bb1 = __ldg(b2 + c0 + 1);
            float2 v0 = make_float2(acc[mt][nt][0] + bb0, acc[mt][nt][1] + bb1);
            float2 v1 = make_float2(acc[mt][nt][2] + bb0, acc[mt][nt][3] + bb1);
            if (r0 < M) *(float2*)(C + (size_t)r0 * 128 + c0) = v0;
            if (r1 < M) *(float2*)(C + (size_t)r1 * 128 + c0) = v1;
        }
    }
}

// ---------------------------------------------------------------------------
extern "C" void kernel_launch(void* const* d_in, const int* in_sizes, int n_in,
                              void* d_out, int out_size) {
    const float* x   = (const float*)d_in[0];
    const int*   ei  = (const int*)d_in[1];
    const float* W1  = (const float*)d_in[2];
    const float* b1  = (const float*)d_in[3];
    const float* W2  = (const float*)d_in[4];
    const float* b2  = (const float*)d_in[5];
    const float* eps = (const float*)d_in[6];
    float*       out = (float*)d_out;

    const int n_nodes = in_sizes[0] / D;
    const int n_edges = in_sizes[1] / 2;
    const int* src = ei;
    const int* dst = ei + n_edges;

    float *h0, *w1t, *w2t;
    cudaGetSymbolAddress((void**)&h0, g_h0);
    cudaGetSymbolAddress((void**)&w1t, g_W1t);
    cudaGetSymbolAddress((void**)&w2t, g_W2t);

    const int SMEM = (TM + 128) * LDS_STRIDE * (int)sizeof(float);  // 202752
    cudaFuncSetAttribute(fused_mlp_kernel,
                         cudaFuncAttributeMaxDynamicSharedMemorySize, SMEM);

    zero_kernel<<<(n_nodes + 255) / 256, 256>>>(n_nodes);

    int n_fill = (n_edges + 255) / 256;
    fill_kernel<<<n_fill + 32, 256>>>(src, dst, n_edges, n_fill,
                                      W1, w1t, W2, w2t);

    int gwarps = (n_nodes * 32 + 255) / 256;
    gather_kernel<<<gwarps, 256>>>(x, eps, h0, n_nodes);

    int gblocks = (n_nodes + TM - 1) / TM;
    fused_mlp_kernel<<<gblocks, 256, SMEM>>>(h0, w1t, b1, w2t, b2, out, n_nodes);
}